// round 7
// baseline (speedup 1.0000x reference)
#include <cuda_runtime.h>
#include <math.h>

typedef unsigned long long ull;

// ---------------- device scratch (no allocations allowed) ----------------
__device__ __align__(16) float g_sub[256];
__device__ __align__(16) float g_gi0[768];
__device__ __align__(16) float g_gh0[768];
__device__ __align__(16) float g_gi[768];          // gi = r0 @ W_ih^T + b_ih (broadcast for all edges)
__device__ __align__(16) float g_obj[1024 * 256];  // per-relation obj table

// self-resetting grid barrier state (generation counter is monotone across graph replays)
__device__ unsigned g_barCnt[4] = {0, 0, 0, 0};
__device__ volatile unsigned g_barGen[4] = {0, 0, 0, 0};

__device__ __forceinline__ void gridbar(int id, unsigned nb) {
    __syncthreads();
    if (threadIdx.x == 0) {
        __threadfence();
        unsigned gen = g_barGen[id];
        unsigned old = atomicAdd(&g_barCnt[id], 1u);
        if (old == nb - 1) {
            g_barCnt[id] = 0;
            __threadfence();
            g_barGen[id] = gen + 1;
        } else {
            while (g_barGen[id] == gen) { __nanosleep(32); }
        }
        __threadfence();
    }
    __syncthreads();
}

__device__ __forceinline__ float warp_reduce(float v) {
#pragma unroll
    for (int o = 16; o; o >>= 1) v += __shfl_xor_sync(0xffffffffu, v, o);
    return v;
}
__device__ __forceinline__ float sigmoidf_(float x) { return 1.0f / (1.0f + expf(-x)); }

// packed fp32x2 FMA (2x FFMA rate on sm_103a; only reachable via PTX)
#define FMA2(c, a, b) asm("fma.rn.f32x2 %0, %1, %2, %0;" : "+l"(c) : "l"(a), "l"(b))

// warp dot: len-256 fp32 dot of x4 (float4*) with row w4 (float4*)
__device__ __forceinline__ float warp_dot256(const float4* __restrict__ x4,
                                             const float4* __restrict__ w4, int lane) {
    float acc = 0.f;
#pragma unroll
    for (int i = 0; i < 2; i++) {
        float4 a = x4[lane + 32 * i];
        float4 b = w4[lane + 32 * i];
        acc += a.x * b.x; acc += a.y * b.y; acc += a.z * b.z; acc += a.w * b.w;
    }
    return warp_reduce(acc);
}

// ============ K_CHAIN: whole seed GRU chain in one kernel (128 blocks) ============
// stage1: sub = tanh(mask@subW^T+subb) [256 dots], gi0 = enc@Wih^T+bih [768 dots]
// stage2: gh0 = sub@Whh^T+bhh [768 dots]
// stage3: r0 = gates(gi0, gh0, sub) (per-block redundant into smem), gi = r0@Wih^T+bih
__global__ __launch_bounds__(256) void kchain(const float* __restrict__ enc,
                                              const float* __restrict__ mask,
                                              const float* __restrict__ subW,
                                              const float* __restrict__ subb,
                                              const float* __restrict__ Wih,
                                              const float* __restrict__ bih,
                                              const float* __restrict__ Whh,
                                              const float* __restrict__ bhh,
                                              const int* __restrict__ seedp,
                                              float* __restrict__ out) {
    __shared__ float s_x[256];
    int tid = threadIdx.x;
    int lane = tid & 31;
    int gw = (int)((blockIdx.x * 256u + tid) >> 5);  // 0..1023
    unsigned nb = gridDim.x;

    // ---- stage 1 ----
    {
        const float4* x4;
        const float4* w4;
        if (gw < 256) { x4 = (const float4*)mask; w4 = (const float4*)(subW + (size_t)gw * 256); }
        else          { x4 = (const float4*)enc;  w4 = (const float4*)(Wih + (size_t)(gw - 256) * 256); }
        float acc = warp_dot256(x4, w4, lane);
        if (lane == 0) {
            if (gw < 256) g_sub[gw] = tanhf(acc + subb[gw]);
            else          g_gi0[gw - 256] = acc + bih[gw - 256];
        }
    }
    gridbar(0, nb);

    // ---- stage 2: gh0 ----
    s_x[tid] = g_sub[tid];
    __syncthreads();
    if (gw < 768) {
        float acc = warp_dot256((const float4*)s_x, (const float4*)(Whh + (size_t)gw * 256), lane);
        if (lane == 0) g_gh0[gw] = acc + bhh[gw];
    }
    gridbar(1, nb);

    // ---- stage 3: r0 (redundant per block, in smem), then gi ----
    {
        int d = tid;
        float r = sigmoidf_(g_gi0[d] + g_gh0[d]);
        float z = sigmoidf_(g_gi0[256 + d] + g_gh0[256 + d]);
        float n = tanhf(g_gi0[512 + d] + r * g_gh0[512 + d]);
        float h = g_sub[d];
        float r0 = (1.f - z) * n + z * h;
        if (blockIdx.x == 0) out[(size_t)seedp[0] * 256 + d] = h;  // out[seed] = sub
        __syncthreads();
        s_x[d] = r0;
    }
    __syncthreads();
    if (gw < 768) {
        float acc = warp_dot256((const float4*)s_x, (const float4*)(Wih + (size_t)gw * 256), lane);
        if (lane == 0) g_gi[gw] = acc + bih[gw];
    }
}

// ============ K_TABLES: block-local relation table (8 relations per block) ============
// Per block: gh[8][768] = relT[8]@Whh^T+bhh  (smem) -> gates -> rj[8][256] (smem)
//            obj[8][256] = tanh(rj@objW^T+objb) -> global g_obj
// Dynamic smem layout:
//   gh   : 8*768 floats          (24576 B)
//   rj   : 8*256 floats          ( 8192 B)
//   aT   : 8*256 floats (relT)   ( 8192 B)
//   sh_b : ull[32][129]          (33024 B)
//   gis  : 768 floats            ( 3072 B)
#define TBL_SMEM_BYTES (24576 + 8192 + 8192 + 33024 + 3072)

__global__ __launch_bounds__(256) void ktables(const float* __restrict__ relT,
                                               const float* __restrict__ Whh,
                                               const float* __restrict__ bhh,
                                               const float* __restrict__ objW,
                                               const float* __restrict__ objb,
                                               int R) {
    extern __shared__ char smem_raw[];
    float* gh = (float*)smem_raw;                       // [8][768]
    float* rj = gh + 8 * 768;                           // [8][256]
    float* aT = rj + 8 * 256;                           // [8][256]
    ull (*sh_b)[129] = (ull(*)[129])(aT + 8 * 256);     // [32][129]
    float* gis = (float*)((char*)sh_b + 33024);         // [768]

    int tid = threadIdx.x;
    int relBase = blockIdx.x * 8;
    int tx = tid & 63;   // col lane: j = jBase+tx, jBase+tx+64
    int ty = tid >> 6;   // row group: rows {ty, ty+4}

    // stage in gi (3KB) and relT rows (8KB)
    if (tid < 192) {
        float4 v = *((const float4*)g_gi + tid);
        *((float4*)gis + tid) = v;
    }
#pragma unroll
    for (int i = 0; i < 2; i++) {
        int idx = tid + 256 * i;                // float4 index over 8*64
        int row = idx >> 6, f4 = idx & 63;
        int rel = relBase + row; if (rel >= R) rel = R - 1;
        float4 v = *((const float4*)(relT + (size_t)rel * 256) + f4);
        *((float4*)(aT + row * 256) + f4) = v;
    }
    __syncthreads();

    const ull* a_ull = (const ull*)aT;  // row stride 128 ull

    // ---- GEMM1: gh = aT @ Whh^T + bhh, N=768 (6 col chunks of 128) ----
#pragma unroll 1
    for (int jc = 0; jc < 6; jc++) {
        int jBase = jc * 128;
        ull c[2][2] = {};
#pragma unroll 1
        for (int kc = 0; kc < 256; kc += 64) {
#pragma unroll
            for (int i = 0; i < 8; i++) {
                int idx = tid + 256 * i;
                int jrow = idx >> 4, f4 = idx & 15;
                float4 v = *(const float4*)(Whh + (size_t)(jBase + jrow) * 256 + kc + f4 * 4);
                sh_b[f4 * 2][jrow]     = ((ull)__float_as_uint(v.y) << 32) | (ull)__float_as_uint(v.x);
                sh_b[f4 * 2 + 1][jrow] = ((ull)__float_as_uint(v.w) << 32) | (ull)__float_as_uint(v.z);
            }
            __syncthreads();
            const ull* a0 = a_ull + (size_t)ty * 128 + kc / 2;
            const ull* a1 = a_ull + (size_t)(ty + 4) * 128 + kc / 2;
#pragma unroll
            for (int k2 = 0; k2 < 32; k2++) {
                ull w0 = sh_b[k2][tx];
                ull w1 = sh_b[k2][tx + 64];
                ull h;
                h = a0[k2]; FMA2(c[0][0], h, w0); FMA2(c[0][1], h, w1);
                h = a1[k2]; FMA2(c[1][0], h, w0); FMA2(c[1][1], h, w1);
            }
            __syncthreads();
        }
#pragma unroll
        for (int a = 0; a < 2; a++) {
            int row = ty + a * 4;
#pragma unroll
            for (int jj = 0; jj < 2; jj++) {
                int j = jBase + tx + jj * 64;
                float lo = __uint_as_float((unsigned)(c[a][jj] & 0xffffffffu));
                float hi = __uint_as_float((unsigned)(c[a][jj] >> 32));
                gh[row * 768 + j] = lo + hi + bhh[j];
            }
        }
    }
    __syncthreads();

    // ---- gates: rj = GRU(gi, gh, relT) ----
#pragma unroll
    for (int i = 0; i < 8; i++) {
        int idx = tid + 256 * i;           // over 8*256
        int rr = idx >> 8, d = idx & 255;
        const float* ghr = gh + rr * 768;
        float r = sigmoidf_(gis[d] + ghr[d]);
        float z = sigmoidf_(gis[256 + d] + ghr[256 + d]);
        float n = tanhf(gis[512 + d] + r * ghr[512 + d]);
        float h = aT[rr * 256 + d];
        rj[rr * 256 + d] = (1.f - z) * n + z * h;
    }
    __syncthreads();

    const ull* rj_ull = (const ull*)rj;

    // ---- GEMM2: obj = tanh(rj @ objW^T + objb), N=256 (2 col chunks) ----
#pragma unroll 1
    for (int jc = 0; jc < 2; jc++) {
        int jBase = jc * 128;
        ull c[2][2] = {};
#pragma unroll 1
        for (int kc = 0; kc < 256; kc += 64) {
#pragma unroll
            for (int i = 0; i < 8; i++) {
                int idx = tid + 256 * i;
                int jrow = idx >> 4, f4 = idx & 15;
                float4 v = *(const float4*)(objW + (size_t)(jBase + jrow) * 256 + kc + f4 * 4);
                sh_b[f4 * 2][jrow]     = ((ull)__float_as_uint(v.y) << 32) | (ull)__float_as_uint(v.x);
                sh_b[f4 * 2 + 1][jrow] = ((ull)__float_as_uint(v.w) << 32) | (ull)__float_as_uint(v.z);
            }
            __syncthreads();
            const ull* a0 = rj_ull + (size_t)ty * 128 + kc / 2;
            const ull* a1 = rj_ull + (size_t)(ty + 4) * 128 + kc / 2;
#pragma unroll
            for (int k2 = 0; k2 < 32; k2++) {
                ull w0 = sh_b[k2][tx];
                ull w1 = sh_b[k2][tx + 64];
                ull h;
                h = a0[k2]; FMA2(c[0][0], h, w0); FMA2(c[0][1], h, w1);
                h = a1[k2]; FMA2(c[1][0], h, w0); FMA2(c[1][1], h, w1);
            }
            __syncthreads();
        }
#pragma unroll
        for (int a = 0; a < 2; a++) {
            int row = ty + a * 4;
            int rel = relBase + row;
            if (rel >= R) continue;
#pragma unroll
            for (int jj = 0; jj < 2; jj++) {
                int j = jBase + tx + jj * 64;
                float lo = __uint_as_float((unsigned)(c[a][jj] & 0xffffffffu));
                float hi = __uint_as_float((unsigned)(c[a][jj] >> 32));
                g_obj[(size_t)rel * 256 + j] = tanhf(lo + hi + objb[j]);
            }
        }
    }
}

// ---------------- K6: per-edge gather/scatter (DRAM-bound) ----------------
__global__ __launch_bounds__(256) void k6(const float* __restrict__ ent,
                                          const int* __restrict__ rel_ids,
                                          const int* __restrict__ tail_ids,
                                          const int* __restrict__ st,
                                          const int* __restrict__ orig,
                                          float* __restrict__ out, int E) {
    int w = (blockIdx.x * 256 + threadIdx.x) >> 5;
    int lane = threadIdx.x & 31;
    if (w >= E) return;
    float4* dst = (float4*)(out + (size_t)tail_ids[w] * 256);
    if (st[w] == 1) {
        const float4* src = (const float4*)(ent + (size_t)orig[w] * 256);
        float4 a = __ldcs(src + lane);
        float4 b = __ldcs(src + lane + 32);
        __stcs(dst + lane, a);
        __stcs(dst + lane + 32, b);
    } else {
        const float4* src = (const float4*)(g_obj + (size_t)rel_ids[w] * 256);
        float4 a = __ldg(src + lane);
        float4 b = __ldg(src + lane + 32);
        __stcs(dst + lane, a);
        __stcs(dst + lane + 32, b);
    }
}

// ---------------- launch ----------------
extern "C" void kernel_launch(void* const* d_in, const int* in_sizes, int n_in,
                              void* d_out, int out_size) {
    const float* enc   = (const float*)d_in[0];
    const float* mask  = (const float*)d_in[1];
    const float* ent   = (const float*)d_in[2];
    const float* relT  = (const float*)d_in[3];
    const float* Wih   = (const float*)d_in[4];
    const float* Whh   = (const float*)d_in[5];
    const float* bih   = (const float*)d_in[6];
    const float* bhh   = (const float*)d_in[7];
    const float* subW  = (const float*)d_in[8];
    const float* subb  = (const float*)d_in[9];
    const float* objW  = (const float*)d_in[10];
    const float* objb  = (const float*)d_in[11];
    const int* rel_ids  = (const int*)d_in[12];
    const int* tail_ids = (const int*)d_in[13];
    const int* tstate   = (const int*)d_in[14];
    const int* orig     = (const int*)d_in[15];
    const int* seedp    = (const int*)d_in[16];
    float* out = (float*)d_out;

    int E = in_sizes[12];
    int R = in_sizes[3] / 256;
    if (R > 1024) R = 1024;

    static bool attr_done = false;
    if (!attr_done) {
        cudaFuncSetAttribute(ktables, cudaFuncAttributeMaxDynamicSharedMemorySize, TBL_SMEM_BYTES);
        attr_done = true;
    }

    // 1) seed GRU chain (internal grid barriers, 128 co-resident blocks)
    kchain<<<128, 256>>>(enc, mask, subW, subb, Wih, bih, Whh, bhh, seedp, out);

    // 2) per-relation obj table, fully block-local
    int tblocks = (R + 7) / 8;
    ktables<<<tblocks, 256, TBL_SMEM_BYTES>>>(relT, Whh, bhh, objW, objb, R);

    // 3) main scatter
    int blocks = (E + 7) / 8;
    k6<<<blocks, 256>>>(ent, rel_ids, tail_ids, tstate, orig, out, E);
}

// round 9
// speedup vs baseline: 1.1267x; 1.1267x over previous
#include <cuda_runtime.h>
#include <math.h>

typedef unsigned long long ull;

// ---------------- device scratch (no allocations allowed) ----------------
__device__ __align__(16) float g_sub[256];
__device__ __align__(16) float g_gi0[768];
__device__ __align__(16) float g_gh0[768];
__device__ __align__(16) float g_gi[768];          // gi = r0 @ W_ih^T + b_ih
__device__ __align__(16) float g_gh[1024 * 768];   // per-relation gh table
__device__ __align__(16) float g_rj[1024 * 256];   // per-relation rj table
__device__ __align__(16) float g_obj[1024 * 256];  // per-relation obj table

// self-resetting grid barrier (generation counter monotone across graph replays)
__device__ unsigned g_barCnt[4] = {0, 0, 0, 0};
__device__ volatile unsigned g_barGen[4] = {0, 0, 0, 0};

__device__ __forceinline__ void gridbar(int id, unsigned nb) {
    __syncthreads();
    if (threadIdx.x == 0) {
        __threadfence();
        unsigned gen = g_barGen[id];
        unsigned old = atomicAdd(&g_barCnt[id], 1u);
        if (old == nb - 1) {
            g_barCnt[id] = 0;
            __threadfence();
            g_barGen[id] = gen + 1;
        } else {
            while (g_barGen[id] == gen) { __nanosleep(32); }
        }
        __threadfence();
    }
    __syncthreads();
}

__device__ __forceinline__ float warp_reduce(float v) {
#pragma unroll
    for (int o = 16; o; o >>= 1) v += __shfl_xor_sync(0xffffffffu, v, o);
    return v;
}
__device__ __forceinline__ float sigmoidf_(float x) { return 1.0f / (1.0f + expf(-x)); }

// packed fp32x2 FMA (2x FFMA rate on sm_103a; only reachable via PTX)
#define FMA2(c, a, b) asm("fma.rn.f32x2 %0, %1, %2, %0;" : "+l"(c) : "l"(a), "l"(b))

__device__ __forceinline__ float warp_dot256(const float4* __restrict__ x4,
                                             const float4* __restrict__ w4, int lane) {
    float acc = 0.f;
#pragma unroll
    for (int i = 0; i < 2; i++) {
        float4 a = x4[lane + 32 * i];
        float4 b = w4[lane + 32 * i];
        acc += a.x * b.x; acc += a.y * b.y; acc += a.z * b.z; acc += a.w * b.w;
    }
    return warp_reduce(acc);
}

// ============ K_CHAIN: whole seed GRU chain, one kernel (128 blocks, 2 grid barriers) ====
__global__ __launch_bounds__(256) void kchain(const float* __restrict__ enc,
                                              const float* __restrict__ mask,
                                              const float* __restrict__ subW,
                                              const float* __restrict__ subb,
                                              const float* __restrict__ Wih,
                                              const float* __restrict__ bih,
                                              const float* __restrict__ Whh,
                                              const float* __restrict__ bhh,
                                              const int* __restrict__ seedp,
                                              float* __restrict__ out) {
    __shared__ float s_x[256];
    int tid = threadIdx.x;
    int lane = tid & 31;
    int gw = (int)((blockIdx.x * 256u + tid) >> 5);  // 0..1023
    unsigned nb = gridDim.x;

    // stage 1: sub (256 dots) + gi0 (768 dots)
    {
        const float4* x4;
        const float4* w4;
        if (gw < 256) { x4 = (const float4*)mask; w4 = (const float4*)(subW + (size_t)gw * 256); }
        else          { x4 = (const float4*)enc;  w4 = (const float4*)(Wih + (size_t)(gw - 256) * 256); }
        float acc = warp_dot256(x4, w4, lane);
        if (lane == 0) {
            if (gw < 256) g_sub[gw] = tanhf(acc + subb[gw]);
            else          g_gi0[gw - 256] = acc + bih[gw - 256];
        }
    }
    gridbar(0, nb);

    // stage 2: gh0 = sub @ Whh^T + bhh
    s_x[tid] = g_sub[tid];
    __syncthreads();
    if (gw < 768) {
        float acc = warp_dot256((const float4*)s_x, (const float4*)(Whh + (size_t)gw * 256), lane);
        if (lane == 0) g_gh0[gw] = acc + bhh[gw];
    }
    gridbar(1, nb);

    // stage 3: r0 gates (per-block redundant, smem), gi = r0 @ Wih^T + bih
    {
        int d = tid;
        float r = sigmoidf_(g_gi0[d] + g_gh0[d]);
        float z = sigmoidf_(g_gi0[256 + d] + g_gh0[256 + d]);
        float n = tanhf(g_gi0[512 + d] + r * g_gh0[512 + d]);
        float h = g_sub[d];
        float r0 = (1.f - z) * n + z * h;
        if (blockIdx.x == 0) out[(size_t)seedp[0] * 256 + d] = h;  // out[seed] = sub
        __syncthreads();
        s_x[d] = r0;
    }
    __syncthreads();
    if (gw < 768) {
        float acc = warp_dot256((const float4*)s_x, (const float4*)(Wih + (size_t)gw * 256), lane);
        if (lane == 0) g_gi[gw] = acc + bih[gw];
    }
}

// ============ KGEMM (R5 form): C[R,N] = act(A[R,256] @ B[N,256]^T + bias) ============
// Block tile: 16 rows x 128 cols, k-chunks of 64, per-thread 4x2 register tile, f32x2 FMA.
// MODE 0: A=relT -> g_gh, N=768, no act.  MODE 1: A=g_rj -> g_obj, N=256, tanh.
template <int N, int MODE>
__global__ __launch_bounds__(256) void kgemm(const float* __restrict__ Aarg,
                                             const float* __restrict__ B,
                                             const float* __restrict__ bias,
                                             int R) {
    __shared__ float sh_a[16][64];
    __shared__ ull sh_b[32][129];

    const float* A = (MODE == 0) ? Aarg : g_rj;
    float* C = (MODE == 0) ? g_gh : g_obj;

    int tid = threadIdx.x;
    int relBase = blockIdx.y * 16;
    int jBase = blockIdx.x * 128;
    int tx = tid & 63;
    int ty = tid >> 6;

    ull c[4][2] = {};

    for (int kc = 0; kc < 256; kc += 64) {
        {
            int row = tid >> 4, f4 = tid & 15;
            int rel = relBase + row;
            if (rel >= R) rel = R - 1;
            float4 v = *(const float4*)(A + (size_t)rel * 256 + kc + f4 * 4);
            *((float4*)sh_a[row] + f4) = v;
        }
#pragma unroll
        for (int i = 0; i < 8; i++) {
            int idx = tid + 256 * i;
            int jrow = idx >> 4, f4 = idx & 15;
            float4 v = *(const float4*)(B + (size_t)(jBase + jrow) * 256 + kc + f4 * 4);
            sh_b[f4 * 2][jrow]     = ((ull)__float_as_uint(v.y) << 32) | (ull)__float_as_uint(v.x);
            sh_b[f4 * 2 + 1][jrow] = ((ull)__float_as_uint(v.w) << 32) | (ull)__float_as_uint(v.z);
        }
        __syncthreads();

        const ull* a0 = (const ull*)sh_a[4 * ty + 0];
        const ull* a1 = (const ull*)sh_a[4 * ty + 1];
        const ull* a2 = (const ull*)sh_a[4 * ty + 2];
        const ull* a3 = (const ull*)sh_a[4 * ty + 3];
#pragma unroll
        for (int k2 = 0; k2 < 32; k2++) {
            ull w0 = sh_b[k2][tx];
            ull w1 = sh_b[k2][tx + 64];
            ull h;
            h = a0[k2]; FMA2(c[0][0], h, w0); FMA2(c[0][1], h, w1);
            h = a1[k2]; FMA2(c[1][0], h, w0); FMA2(c[1][1], h, w1);
            h = a2[k2]; FMA2(c[2][0], h, w0); FMA2(c[2][1], h, w1);
            h = a3[k2]; FMA2(c[3][0], h, w0); FMA2(c[3][1], h, w1);
        }
        __syncthreads();
    }

#pragma unroll
    for (int a = 0; a < 4; a++) {
        int rel = relBase + 4 * ty + a;
        if (rel >= R) continue;
#pragma unroll
        for (int jj = 0; jj < 2; jj++) {
            int j = jBase + tx + jj * 64;
            float lo = __uint_as_float((unsigned)(c[a][jj] & 0xffffffffu));
            float hi = __uint_as_float((unsigned)(c[a][jj] >> 32));
            float s = lo + hi + bias[j];
            if (MODE == 1) s = tanhf(s);
            C[(size_t)rel * N + j] = s;
        }
    }
}

// ---------------- K5b: gates per relation -> g_rj ----------------
__global__ __launch_bounds__(256) void k5b(const float* __restrict__ relT, int R) {
    int rel = blockIdx.x;
    if (rel >= R) return;
    int d = threadIdx.x;
    const float* gh = g_gh + (size_t)rel * 768;
    float r = sigmoidf_(g_gi[d] + gh[d]);
    float z = sigmoidf_(g_gi[256 + d] + gh[256 + d]);
    float n = tanhf(g_gi[512 + d] + r * gh[512 + d]);
    float h = relT[(size_t)rel * 256 + d];
    g_rj[(size_t)rel * 256 + d] = (1.f - z) * n + z * h;
}

// ---------------- K6: per-edge gather/scatter, 4 edges per warp (MLP=8) ----------------
__global__ __launch_bounds__(256) void k6(const float* __restrict__ ent,
                                          const int* __restrict__ rel_ids,
                                          const int* __restrict__ tail_ids,
                                          const int* __restrict__ st,
                                          const int* __restrict__ orig,
                                          float* __restrict__ out, int E) {
    int warp = (blockIdx.x * 256 + threadIdx.x) >> 5;
    int lane = threadIdx.x & 31;
    int e0 = warp * 4;
    if (e0 >= E) return;

    if (e0 + 4 <= E) {
        // vector index loads (e0 % 4 == 0 -> 16B aligned)
        int4 st4 = *(const int4*)(st + e0);
        int4 or4 = *(const int4*)(orig + e0);
        int4 rl4 = *(const int4*)(rel_ids + e0);
        int4 tl4 = *(const int4*)(tail_ids + e0);
        int sts[4]  = {st4.x, st4.y, st4.z, st4.w};
        int orgs[4] = {or4.x, or4.y, or4.z, or4.w};
        int rls[4]  = {rl4.x, rl4.y, rl4.z, rl4.w};
        int tls[4]  = {tl4.x, tl4.y, tl4.z, tl4.w};

        float4 a[4], b[4];
#pragma unroll
        for (int i = 0; i < 4; i++) {
            const float4* src = (sts[i] == 1)
                ? (const float4*)(ent + (size_t)orgs[i] * 256)
                : (const float4*)(g_obj + (size_t)rls[i] * 256);
            a[i] = __ldg(src + lane);
            b[i] = __ldg(src + lane + 32);
        }
#pragma unroll
        for (int i = 0; i < 4; i++) {
            float4* dst = (float4*)(out + (size_t)tls[i] * 256);
            __stcs(dst + lane, a[i]);
            __stcs(dst + lane + 32, b[i]);
        }
    } else {
        for (int e = e0; e < E; e++) {
            const float4* src = (st[e] == 1)
                ? (const float4*)(ent + (size_t)orig[e] * 256)
                : (const float4*)(g_obj + (size_t)rel_ids[e] * 256);
            float4 a = __ldg(src + lane);
            float4 b = __ldg(src + lane + 32);
            float4* dst = (float4*)(out + (size_t)tail_ids[e] * 256);
            __stcs(dst + lane, a);
            __stcs(dst + lane + 32, b);
        }
    }
}

// ---------------- launch ----------------
extern "C" void kernel_launch(void* const* d_in, const int* in_sizes, int n_in,
                              void* d_out, int out_size) {
    const float* enc   = (const float*)d_in[0];
    const float* mask  = (const float*)d_in[1];
    const float* ent   = (const float*)d_in[2];
    const float* relT  = (const float*)d_in[3];
    const float* Wih   = (const float*)d_in[4];
    const float* Whh   = (const float*)d_in[5];
    const float* bih   = (const float*)d_in[6];
    const float* bhh   = (const float*)d_in[7];
    const float* subW  = (const float*)d_in[8];
    const float* subb  = (const float*)d_in[9];
    const float* objW  = (const float*)d_in[10];
    const float* objb  = (const float*)d_in[11];
    const int* rel_ids  = (const int*)d_in[12];
    const int* tail_ids = (const int*)d_in[13];
    const int* tstate   = (const int*)d_in[14];
    const int* orig     = (const int*)d_in[15];
    const int* seedp    = (const int*)d_in[16];
    float* out = (float*)d_out;

    int E = in_sizes[12];
    int R = in_sizes[3] / 256;
    if (R > 1024) R = 1024;

    // 1) seed GRU chain (one kernel, internal grid barriers)
    kchain<<<128, 256>>>(enc, mask, subW, subb, Wih, bih, Whh, bhh, seedp, out);

    // 2) per-relation table: gh -> rj -> obj (weights read once)
    dim3 g_gh_grid(6, (unsigned)((R + 15) / 16));
    kgemm<768, 0><<<g_gh_grid, 256>>>(relT, Whh, bhh, R);
    k5b<<<R, 256>>>(relT, R);
    dim3 g_obj_grid(2, (unsigned)((R + 15) / 16));
    kgemm<256, 1><<<g_obj_grid, 256>>>(nullptr, objW, objb, R);

    // 3) main scatter: 4 edges per warp
    int warps = (E + 3) / 4;
    int blocks = (warps * 32 + 255) / 256;
    k6<<<blocks, 256>>>(ent, rel_ids, tail_ids, tstate, orig, out, E);
}

// round 13
// speedup vs baseline: 1.1709x; 1.0392x over previous
#include <cuda_runtime.h>
#include <math.h>

typedef unsigned long long ull;

// ---------------- device scratch (no allocations allowed) ----------------
__device__ __align__(16) float g_sub[256];
__device__ __align__(16) float g_gi0[768];
__device__ __align__(16) float g_gh0[768];
__device__ __align__(16) float g_gi[768];          // gi = r0 @ W_ih^T + b_ih
__device__ __align__(16) float g_gh[1024 * 768];   // per-relation gh table
__device__ __align__(16) float g_rj[1024 * 256];   // per-relation rj table
__device__ __align__(16) float g_obj[1024 * 256];  // per-relation obj table

// self-resetting grid barrier (generation counter monotone across graph replays)
__device__ unsigned g_barCnt[4] = {0, 0, 0, 0};
__device__ volatile unsigned g_barGen[4] = {0, 0, 0, 0};

__device__ __forceinline__ void gridbar(int id, unsigned nb) {
    __syncthreads();
    if (threadIdx.x == 0) {
        __threadfence();
        unsigned gen = g_barGen[id];
        unsigned old = atomicAdd(&g_barCnt[id], 1u);
        if (old == nb - 1) {
            g_barCnt[id] = 0;
            __threadfence();
            g_barGen[id] = gen + 1;
        } else {
            while (g_barGen[id] == gen) { }
        }
        __threadfence();
    }
    __syncthreads();
}

__device__ __forceinline__ float warp_reduce(float v) {
#pragma unroll
    for (int o = 16; o; o >>= 1) v += __shfl_xor_sync(0xffffffffu, v, o);
    return v;
}
__device__ __forceinline__ float sigmoidf_(float x) { return 1.0f / (1.0f + expf(-x)); }

// packed fp32x2 FMA (2x FFMA rate on sm_103a; only reachable via PTX)
#define FMA2(c, a, b) asm("fma.rn.f32x2 %0, %1, %2, %0;" : "+l"(c) : "l"(a), "l"(b))
#define PACK2(x, y) (((ull)__float_as_uint(y) << 32) | (ull)__float_as_uint(x))

__device__ __forceinline__ float warp_dot256(const float4* __restrict__ x4,
                                             const float4* __restrict__ w4, int lane) {
    float acc = 0.f;
#pragma unroll
    for (int i = 0; i < 2; i++) {
        float4 a = x4[lane + 32 * i];
        float4 b = w4[lane + 32 * i];
        acc += a.x * b.x; acc += a.y * b.y; acc += a.z * b.z; acc += a.w * b.w;
    }
    return warp_reduce(acc);
}

// ============ K_CHAIN: whole seed GRU chain, one kernel (128 blocks, 2 grid barriers) ====
__global__ __launch_bounds__(256) void kchain(const float* __restrict__ enc,
                                              const float* __restrict__ mask,
                                              const float* __restrict__ subW,
                                              const float* __restrict__ subb,
                                              const float* __restrict__ Wih,
                                              const float* __restrict__ bih,
                                              const float* __restrict__ Whh,
                                              const float* __restrict__ bhh,
                                              const int* __restrict__ seedp,
                                              float* __restrict__ out) {
    __shared__ float s_x[256];
    int tid = threadIdx.x;
    int lane = tid & 31;
    int gw = (int)((blockIdx.x * 256u + tid) >> 5);  // 0..1023
    unsigned nb = gridDim.x;

    // stage 1: sub (256 dots) + gi0 (768 dots)
    {
        const float4* x4;
        const float4* w4;
        if (gw < 256) { x4 = (const float4*)mask; w4 = (const float4*)(subW + (size_t)gw * 256); }
        else          { x4 = (const float4*)enc;  w4 = (const float4*)(Wih + (size_t)(gw - 256) * 256); }
        float acc = warp_dot256(x4, w4, lane);
        if (lane == 0) {
            if (gw < 256) g_sub[gw] = tanhf(acc + subb[gw]);
            else          g_gi0[gw - 256] = acc + bih[gw - 256];
        }
    }
    gridbar(0, nb);

    // stage 2: gh0 = sub @ Whh^T + bhh
    s_x[tid] = g_sub[tid];
    __syncthreads();
    if (gw < 768) {
        float acc = warp_dot256((const float4*)s_x, (const float4*)(Whh + (size_t)gw * 256), lane);
        if (lane == 0) g_gh0[gw] = acc + bhh[gw];
    }
    gridbar(1, nb);

    // stage 3: r0 gates (per-block redundant, smem), gi = r0 @ Wih^T + bih
    {
        int d = tid;
        float r = sigmoidf_(g_gi0[d] + g_gh0[d]);
        float z = sigmoidf_(g_gi0[256 + d] + g_gh0[256 + d]);
        float n = tanhf(g_gi0[512 + d] + r * g_gh0[512 + d]);
        float h = g_sub[d];
        float r0 = (1.f - z) * n + z * h;
        if (blockIdx.x == 0) out[(size_t)seedp[0] * 256 + d] = h;  // out[seed] = sub
        __syncthreads();
        s_x[d] = r0;
    }
    __syncthreads();
    if (gw < 768) {
        float acc = warp_dot256((const float4*)s_x, (const float4*)(Wih + (size_t)gw * 256), lane);
        if (lane == 0) g_gi[gw] = acc + bih[gw];
    }
}

// ============ KGEMM16: C[R,768] = A[R,256] @ B^T + bias  (gh), prefetch double-buffer ===
// 16 rows x 128 cols per block; per-thread 4x2 register tile; next A/B tiles prefetched
// into registers to overlap global-load latency with the FMA stage.
__global__ __launch_bounds__(256) void kgemm16(const float* __restrict__ A,
                                               const float* __restrict__ B,
                                               const float* __restrict__ bias,
                                               int R) {
    __shared__ float sh_a[16][64];
    __shared__ ull sh_b[32][129];

    int tid = threadIdx.x;
    int relBase = blockIdx.y * 16;
    int jBase = blockIdx.x * 128;
    int tx = tid & 63;
    int ty = tid >> 6;

    int arow = tid >> 4, af4 = tid & 15;
    int rel0 = relBase + arow; if (rel0 >= R) rel0 = R - 1;
    const float4* Abase = (const float4*)(A + (size_t)rel0 * 256);

    // prefetch kc=0 tiles
    float4 pa = Abase[af4];
    float4 pb[8];
#pragma unroll
    for (int i = 0; i < 8; i++) {
        int idx = tid + 256 * i;
        int jrow = idx >> 4, f4 = idx & 15;
        pb[i] = *(const float4*)(B + (size_t)(jBase + jrow) * 256 + f4 * 4);
    }

    ull c[4][2] = {};

#pragma unroll 1
    for (int kc = 0; kc < 256; kc += 64) {
        *((float4*)sh_a[arow] + af4) = pa;
#pragma unroll
        for (int i = 0; i < 8; i++) {
            int idx = tid + 256 * i;
            int jrow = idx >> 4, f4 = idx & 15;
            sh_b[f4 * 2][jrow]     = PACK2(pb[i].x, pb[i].y);
            sh_b[f4 * 2 + 1][jrow] = PACK2(pb[i].z, pb[i].w);
        }
        __syncthreads();

        if (kc < 192) {  // issue next-tile loads; overlap with compute below
            pa = Abase[af4 + (kc + 64) / 4];
#pragma unroll
            for (int i = 0; i < 8; i++) {
                int idx = tid + 256 * i;
                int jrow = idx >> 4, f4 = idx & 15;
                pb[i] = *(const float4*)(B + (size_t)(jBase + jrow) * 256 + kc + 64 + f4 * 4);
            }
        }

        const ull* a0 = (const ull*)sh_a[4 * ty + 0];
        const ull* a1 = (const ull*)sh_a[4 * ty + 1];
        const ull* a2 = (const ull*)sh_a[4 * ty + 2];
        const ull* a3 = (const ull*)sh_a[4 * ty + 3];
#pragma unroll
        for (int k2 = 0; k2 < 32; k2++) {
            ull w0 = sh_b[k2][tx];
            ull w1 = sh_b[k2][tx + 64];
            ull h;
            h = a0[k2]; FMA2(c[0][0], h, w0); FMA2(c[0][1], h, w1);
            h = a1[k2]; FMA2(c[1][0], h, w0); FMA2(c[1][1], h, w1);
            h = a2[k2]; FMA2(c[2][0], h, w0); FMA2(c[2][1], h, w1);
            h = a3[k2]; FMA2(c[3][0], h, w0); FMA2(c[3][1], h, w1);
        }
        __syncthreads();
    }

#pragma unroll
    for (int a = 0; a < 4; a++) {
        int rel = relBase + 4 * ty + a;
        if (rel >= R) continue;
#pragma unroll
        for (int jj = 0; jj < 2; jj++) {
            int j = jBase + tx + jj * 64;
            float lo = __uint_as_float((unsigned)(c[a][jj] & 0xffffffffu));
            float hi = __uint_as_float((unsigned)(c[a][jj] >> 32));
            g_gh[(size_t)rel * 768 + j] = lo + hi + bias[j];
        }
    }
}

// ============ KGEMM8: obj = tanh(rj @ objW^T + objb), 8 rows x 128 cols, prefetch =======
__global__ __launch_bounds__(256) void kgemm8(const float* __restrict__ B,
                                              const float* __restrict__ bias,
                                              int R) {
    __shared__ float sh_a[8][64];
    __shared__ ull sh_b[32][129];

    int tid = threadIdx.x;
    int relBase = blockIdx.y * 8;
    int jBase = blockIdx.x * 128;
    int tx = tid & 63;
    int ty = tid >> 6;

    int arow = tid >> 4, af4 = tid & 15;   // valid for tid<128
    int rel0 = relBase + arow; if (rel0 >= R) rel0 = R - 1;
    const float4* Abase = (const float4*)(g_rj + (size_t)rel0 * 256);

    float4 pa = make_float4(0.f, 0.f, 0.f, 0.f);
    if (tid < 128) pa = Abase[af4];
    float4 pb[8];
#pragma unroll
    for (int i = 0; i < 8; i++) {
        int idx = tid + 256 * i;
        int jrow = idx >> 4, f4 = idx & 15;
        pb[i] = *(const float4*)(B + (size_t)(jBase + jrow) * 256 + f4 * 4);
    }

    ull c[2][2] = {};

#pragma unroll 1
    for (int kc = 0; kc < 256; kc += 64) {
        if (tid < 128) *((float4*)sh_a[arow] + af4) = pa;
#pragma unroll
        for (int i = 0; i < 8; i++) {
            int idx = tid + 256 * i;
            int jrow = idx >> 4, f4 = idx & 15;
            sh_b[f4 * 2][jrow]     = PACK2(pb[i].x, pb[i].y);
            sh_b[f4 * 2 + 1][jrow] = PACK2(pb[i].z, pb[i].w);
        }
        __syncthreads();

        if (kc < 192) {
            if (tid < 128) pa = Abase[af4 + (kc + 64) / 4];
#pragma unroll
            for (int i = 0; i < 8; i++) {
                int idx = tid + 256 * i;
                int jrow = idx >> 4, f4 = idx & 15;
                pb[i] = *(const float4*)(B + (size_t)(jBase + jrow) * 256 + kc + 64 + f4 * 4);
            }
        }

        const ull* a0 = (const ull*)sh_a[ty];
        const ull* a1 = (const ull*)sh_a[ty + 4];
#pragma unroll
        for (int k2 = 0; k2 < 32; k2++) {
            ull w0 = sh_b[k2][tx];
            ull w1 = sh_b[k2][tx + 64];
            ull h;
            h = a0[k2]; FMA2(c[0][0], h, w0); FMA2(c[0][1], h, w1);
            h = a1[k2]; FMA2(c[1][0], h, w0); FMA2(c[1][1], h, w1);
        }
        __syncthreads();
    }

#pragma unroll
    for (int a = 0; a < 2; a++) {
        int rel = relBase + ty + a * 4;
        if (rel >= R) continue;
#pragma unroll
        for (int jj = 0; jj < 2; jj++) {
            int j = jBase + tx + jj * 64;
            float lo = __uint_as_float((unsigned)(c[a][jj] & 0xffffffffu));
            float hi = __uint_as_float((unsigned)(c[a][jj] >> 32));
            g_obj[(size_t)rel * 256 + j] = tanhf(lo + hi + bias[j]);
        }
    }
}

// ---------------- K5b: gates per relation -> g_rj ----------------
__global__ __launch_bounds__(256) void k5b(const float* __restrict__ relT, int R) {
    int rel = blockIdx.x;
    if (rel >= R) return;
    int d = threadIdx.x;
    const float* gh = g_gh + (size_t)rel * 768;
    float r = sigmoidf_(g_gi[d] + gh[d]);
    float z = sigmoidf_(g_gi[256 + d] + gh[256 + d]);
    float n = tanhf(g_gi[512 + d] + r * gh[512 + d]);
    float h = relT[(size_t)rel * 256 + d];
    g_rj[(size_t)rel * 256 + d] = (1.f - z) * n + z * h;
}

// ---------------- K6: per-edge gather/scatter (R5 form — measured best) ----------------
__global__ __launch_bounds__(256) void k6(const float* __restrict__ ent,
                                          const int* __restrict__ rel_ids,
                                          const int* __restrict__ tail_ids,
                                          const int* __restrict__ st,
                                          const int* __restrict__ orig,
                                          float* __restrict__ out, int E) {
    int w = (blockIdx.x * 256 + threadIdx.x) >> 5;
    int lane = threadIdx.x & 31;
    if (w >= E) return;
    float4* dst = (float4*)(out + (size_t)tail_ids[w] * 256);
    if (st[w] == 1) {
        const float4* src = (const float4*)(ent + (size_t)orig[w] * 256);
        float4 a = __ldcs(src + lane);
        float4 b = __ldcs(src + lane + 32);
        __stcs(dst + lane, a);
        __stcs(dst + lane + 32, b);
    } else {
        const float4* src = (const float4*)(g_obj + (size_t)rel_ids[w] * 256);
        float4 a = __ldg(src + lane);
        float4 b = __ldg(src + lane + 32);
        __stcs(dst + lane, a);
        __stcs(dst + lane + 32, b);
    }
}

// ---------------- launch ----------------
extern "C" void kernel_launch(void* const* d_in, const int* in_sizes, int n_in,
                              void* d_out, int out_size) {
    const float* enc   = (const float*)d_in[0];
    const float* mask  = (const float*)d_in[1];
    const float* ent   = (const float*)d_in[2];
    const float* relT  = (const float*)d_in[3];
    const float* Wih   = (const float*)d_in[4];
    const float* Whh   = (const float*)d_in[5];
    const float* bih   = (const float*)d_in[6];
    const float* bhh   = (const float*)d_in[7];
    const float* subW  = (const float*)d_in[8];
    const float* subb  = (const float*)d_in[9];
    const float* objW  = (const float*)d_in[10];
    const float* objb  = (const float*)d_in[11];
    const int* rel_ids  = (const int*)d_in[12];
    const int* tail_ids = (const int*)d_in[13];
    const int* tstate   = (const int*)d_in[14];
    const int* orig     = (const int*)d_in[15];
    const int* seedp    = (const int*)d_in[16];
    float* out = (float*)d_out;

    int E = in_sizes[12];
    int R = in_sizes[3] / 256;
    if (R > 1024) R = 1024;

    // 1) seed GRU chain (one kernel, internal grid barriers)
    kchain<<<128, 256>>>(enc, mask, subW, subb, Wih, bih, Whh, bhh, seedp, out);

    // 2) per-relation table: gh -> rj -> obj
    dim3 gh_grid(6, (unsigned)((R + 15) / 16));
    kgemm16<<<gh_grid, 256>>>(relT, Whh, bhh, R);
    k5b<<<R, 256>>>(relT, R);
    dim3 obj_grid(2, (unsigned)((R + 7) / 8));
    kgemm8<<<obj_grid, 256>>>(objW, objb, R);

    // 3) main scatter (1 edge per warp)
    int blocks = (E + 7) / 8;
    k6<<<blocks, 256>>>(ent, rel_ids, tail_ids, tstate, orig, out, E);
}